// round 6
// baseline (speedup 1.0000x reference)
#include <cuda_runtime.h>
#include <math.h>
#include <stdint.h>
#include <stddef.h>

// Problem dims (fixed)
#define N_ROIS 4096
#define N_BANK 8192
#define QDIM   2048
#define DIM_IN 2048
#define LATENT 1024

// ---------------------------------------------------------------------------
// Scratch (device globals; no runtime allocation allowed)
// ---------------------------------------------------------------------------
__device__ float g_q1[N_ROIS * LATENT];
__device__ float g_q2[N_ROIS * LATENT];
__device__ float g_k1[N_BANK * LATENT];
__device__ float g_v1[N_BANK * LATENT];
__device__ float g_k2[N_BANK * LATENT];
__device__ float g_v2[N_BANK * LATENT];
__device__ float g_sc[(size_t)N_ROIS * N_BANK];   // 128 MB score scratch (reused)
__device__ float g_f1[N_ROIS * LATENT];
__device__ float g_f2[N_ROIS * LATENT];
__device__ float g_x [N_ROIS * LATENT];

// ---------------------------------------------------------------------------
// Double-buffered SGEMM: C[m,n] = alpha * sum_k A[m,k]*Bop[k,n] + bias[n]
//   BT=1 : B is [N,K] row-major (torch Linear weight) -> "NT"
//   BT=0 : B is [K,N] row-major                        -> "NN"
// 128x128 tile, BK=16, 256 threads, 8x8 per-thread microtile.
// One __syncthreads per K-step; next tile staged in registers during compute.
// All dims must be multiples of 128 (true for this problem).
// ---------------------------------------------------------------------------
template <int BT>
__global__ void __launch_bounds__(256)
gemm128(const float* __restrict__ A, const float* __restrict__ B,
        const float* __restrict__ bias, float* __restrict__ C,
        int M, int N, int K, float alpha)
{
    constexpr int BK = 16;
    __shared__ float As[2][BK][128];
    __shared__ float Bs[2][BK][128];

    const int tid = threadIdx.x;
    const int bm = blockIdx.y * 128;
    const int bn = blockIdx.x * 128;
    const int tr = (tid >> 4) << 3;   // 0..120
    const int tc = (tid & 15) << 3;   // 0..120

    // loader indices (A-tile & NT B-tile: 128 rows x 16 cols)
    const int lr = tid >> 2;          // 0..63
    const int lc = (tid & 3) << 2;    // 0,4,8,12
    // NN B-tile: 16 rows x 128 cols
    const int br = tid >> 5;          // 0..7
    const int bc = (tid & 31) << 2;   // 0..124

    float acc[8][8];
#pragma unroll
    for (int i = 0; i < 8; i++)
#pragma unroll
        for (int j = 0; j < 8; j++) acc[i][j] = 0.f;

    const int T = K / BK;

    // ---- prologue: load tile 0 directly into buffer 0 ----
    {
        const int k0 = 0;
#pragma unroll
        for (int i = 0; i < 2; i++) {
            int r = lr + i * 64;
            float4 v = *(const float4*)(A + (size_t)(bm + r) * K + k0 + lc);
            As[0][lc + 0][r] = v.x;
            As[0][lc + 1][r] = v.y;
            As[0][lc + 2][r] = v.z;
            As[0][lc + 3][r] = v.w;
        }
        if (BT) {
#pragma unroll
            for (int i = 0; i < 2; i++) {
                int r = lr + i * 64;   // n index
                float4 v = *(const float4*)(B + (size_t)(bn + r) * K + k0 + lc);
                Bs[0][lc + 0][r] = v.x;
                Bs[0][lc + 1][r] = v.y;
                Bs[0][lc + 2][r] = v.z;
                Bs[0][lc + 3][r] = v.w;
            }
        } else {
#pragma unroll
            for (int i = 0; i < 2; i++) {
                int r = br + i * 8;    // k index
                *(float4*)&Bs[0][r][bc] =
                    *(const float4*)(B + (size_t)(k0 + r) * N + bn + bc);
            }
        }
    }
    __syncthreads();

    for (int t = 0; t < T; t++) {
        const int cur = t & 1;
        const bool has_next = (t + 1 < T);

        // ---- stage next tile into registers (overlaps with compute below) ----
        float4 a_stg[2], b_stg[2];
        if (has_next) {
            const int k0 = (t + 1) * BK;
#pragma unroll
            for (int i = 0; i < 2; i++) {
                int r = lr + i * 64;
                a_stg[i] = *(const float4*)(A + (size_t)(bm + r) * K + k0 + lc);
            }
            if (BT) {
#pragma unroll
                for (int i = 0; i < 2; i++) {
                    int r = lr + i * 64;
                    b_stg[i] = *(const float4*)(B + (size_t)(bn + r) * K + k0 + lc);
                }
            } else {
#pragma unroll
                for (int i = 0; i < 2; i++) {
                    int r = br + i * 8;
                    b_stg[i] = *(const float4*)(B + (size_t)(k0 + r) * N + bn + bc);
                }
            }
        }

        // ---- compute on current buffer ----
#pragma unroll
        for (int kk = 0; kk < BK; kk++) {
            float4 a0 = *(const float4*)&As[cur][kk][tr];
            float4 a1 = *(const float4*)&As[cur][kk][tr + 4];
            float4 b0 = *(const float4*)&Bs[cur][kk][tc];
            float4 b1 = *(const float4*)&Bs[cur][kk][tc + 4];
            float ra[8] = {a0.x, a0.y, a0.z, a0.w, a1.x, a1.y, a1.z, a1.w};
            float rb[8] = {b0.x, b0.y, b0.z, b0.w, b1.x, b1.y, b1.z, b1.w};
#pragma unroll
            for (int i = 0; i < 8; i++)
#pragma unroll
                for (int j = 0; j < 8; j++)
                    acc[i][j] = fmaf(ra[i], rb[j], acc[i][j]);
        }

        // ---- commit staged tile to the other buffer ----
        if (has_next) {
            const int nb = cur ^ 1;
#pragma unroll
            for (int i = 0; i < 2; i++) {
                int r = lr + i * 64;
                As[nb][lc + 0][r] = a_stg[i].x;
                As[nb][lc + 1][r] = a_stg[i].y;
                As[nb][lc + 2][r] = a_stg[i].z;
                As[nb][lc + 3][r] = a_stg[i].w;
            }
            if (BT) {
#pragma unroll
                for (int i = 0; i < 2; i++) {
                    int r = lr + i * 64;
                    Bs[nb][lc + 0][r] = b_stg[i].x;
                    Bs[nb][lc + 1][r] = b_stg[i].y;
                    Bs[nb][lc + 2][r] = b_stg[i].z;
                    Bs[nb][lc + 3][r] = b_stg[i].w;
                }
            } else {
#pragma unroll
                for (int i = 0; i < 2; i++) {
                    int r = br + i * 8;
                    *(float4*)&Bs[nb][r][bc] = b_stg[i];
                }
            }
        }
        __syncthreads();
    }

    float bv[8];
#pragma unroll
    for (int j = 0; j < 8; j++) bv[j] = bias ? bias[bn + tc + j] : 0.f;

#pragma unroll
    for (int i = 0; i < 8; i++) {
        float* crow = C + (size_t)(bm + tr + i) * N + bn + tc;
        float4 o0, o1;
        o0.x = fmaf(acc[i][0], alpha, bv[0]);
        o0.y = fmaf(acc[i][1], alpha, bv[1]);
        o0.z = fmaf(acc[i][2], alpha, bv[2]);
        o0.w = fmaf(acc[i][3], alpha, bv[3]);
        o1.x = fmaf(acc[i][4], alpha, bv[4]);
        o1.y = fmaf(acc[i][5], alpha, bv[5]);
        o1.z = fmaf(acc[i][6], alpha, bv[6]);
        o1.w = fmaf(acc[i][7], alpha, bv[7]);
        *(float4*)(crow)     = o0;
        *(float4*)(crow + 4) = o1;
    }
}

// ---------------------------------------------------------------------------
// Row softmax over 8192 columns. One block (256 threads) per row; the whole
// row lives in registers (32 floats / thread).
// ---------------------------------------------------------------------------
__global__ void __launch_bounds__(256)
softmax8192(float* __restrict__ S)
{
    __shared__ float red[256];
    const int row = blockIdx.x;
    const int tid = threadIdx.x;
    float* p = S + (size_t)row * N_BANK;

    float4 v[8];
    float lmax = -3.402823466e38f;
#pragma unroll
    for (int i = 0; i < 8; i++) {
        v[i] = *(const float4*)(p + (size_t)(i * 256 + tid) * 4);
        lmax = fmaxf(lmax, fmaxf(fmaxf(v[i].x, v[i].y), fmaxf(v[i].z, v[i].w)));
    }
    red[tid] = lmax;
    __syncthreads();
    for (int s = 128; s > 0; s >>= 1) {
        if (tid < s) red[tid] = fmaxf(red[tid], red[tid + s]);
        __syncthreads();
    }
    const float m = red[0];
    __syncthreads();

    float lsum = 0.f;
#pragma unroll
    for (int i = 0; i < 8; i++) {
        v[i].x = __expf(v[i].x - m);
        v[i].y = __expf(v[i].y - m);
        v[i].z = __expf(v[i].z - m);
        v[i].w = __expf(v[i].w - m);
        lsum += (v[i].x + v[i].y) + (v[i].z + v[i].w);
    }
    red[tid] = lsum;
    __syncthreads();
    for (int s = 128; s > 0; s >>= 1) {
        if (tid < s) red[tid] += red[tid + s];
        __syncthreads();
    }
    const float inv = 1.f / red[0];

#pragma unroll
    for (int i = 0; i < 8; i++) {
        v[i].x *= inv; v[i].y *= inv; v[i].z *= inv; v[i].w *= inv;
        *(float4*)(p + (size_t)(i * 256 + tid) * 4) = v[i];
    }
}

// ---------------------------------------------------------------------------
// Gate + LayerNorm + PReLU:  x = PReLU(LN(f1*f2))
// One block (256 threads) per row of 1024.
// ---------------------------------------------------------------------------
__global__ void __launch_bounds__(256)
gate_ln_prelu(const float* __restrict__ f1, const float* __restrict__ f2,
              const float* __restrict__ lnw, const float* __restrict__ lnb,
              const float* __restrict__ pa, float* __restrict__ x)
{
    __shared__ float red[256];
    const int row = blockIdx.x;
    const int tid = threadIdx.x;
    const size_t off = (size_t)row * LATENT + tid * 4;

    float4 a = *(const float4*)(f1 + off);
    float4 b = *(const float4*)(f2 + off);
    float c0 = a.x * b.x, c1 = a.y * b.y, c2 = a.z * b.z, c3 = a.w * b.w;

    red[tid] = (c0 + c1) + (c2 + c3);
    __syncthreads();
    for (int s = 128; s > 0; s >>= 1) {
        if (tid < s) red[tid] += red[tid + s];
        __syncthreads();
    }
    const float mu = red[0] * (1.0f / LATENT);
    __syncthreads();

    float d0 = c0 - mu, d1 = c1 - mu, d2 = c2 - mu, d3 = c3 - mu;
    red[tid] = (d0 * d0 + d1 * d1) + (d2 * d2 + d3 * d3);
    __syncthreads();
    for (int s = 128; s > 0; s >>= 1) {
        if (tid < s) red[tid] += red[tid + s];
        __syncthreads();
    }
    const float rstd = rsqrtf(red[0] * (1.0f / LATENT) + 1e-5f);

    float4 w  = *(const float4*)(lnw + tid * 4);
    float4 bb = *(const float4*)(lnb + tid * 4);
    const float slope = pa[0];

    float y0 = fmaf(d0 * rstd, w.x, bb.x);
    float y1 = fmaf(d1 * rstd, w.y, bb.y);
    float y2 = fmaf(d2 * rstd, w.z, bb.z);
    float y3 = fmaf(d3 * rstd, w.w, bb.w);
    y0 = (y0 >= 0.f) ? y0 : slope * y0;
    y1 = (y1 >= 0.f) ? y1 : slope * y1;
    y2 = (y2 >= 0.f) ? y2 : slope * y2;
    y3 = (y3 >= 0.f) ? y3 : slope * y3;

    float4 o = {y0, y1, y2, y3};
    *(float4*)(x + off) = o;
}

// ---------------------------------------------------------------------------
// Launch
// ---------------------------------------------------------------------------
extern "C" void kernel_launch(void* const* d_in, const int* in_sizes, int n_in,
                              void* d_out, int out_size)
{
    const float* feat = (const float*)d_in[0];
    const float* bank = (const float*)d_in[1];
    const float* Wc1 = (const float*)d_in[2];  const float* bc1 = (const float*)d_in[3];
    const float* Wc2 = (const float*)d_in[4];  const float* bc2 = (const float*)d_in[5];
    const float* Wc3 = (const float*)d_in[6];  const float* bc3 = (const float*)d_in[7];
    const float* Wd1 = (const float*)d_in[8];  const float* bd1 = (const float*)d_in[9];
    const float* Wd2 = (const float*)d_in[10]; const float* bd2 = (const float*)d_in[11];
    const float* Wd3 = (const float*)d_in[12]; const float* bd3 = (const float*)d_in[13];
    const float* lnw = (const float*)d_in[14]; const float* lnb = (const float*)d_in[15];
    const float* pa  = (const float*)d_in[16];
    const float* Wffn = (const float*)d_in[17]; const float* bffn = (const float*)d_in[18];
    float* out = (float*)d_out;

    float *q1, *q2, *k1, *v1, *k2, *v2, *sc, *f1, *f2, *x;
    cudaGetSymbolAddress((void**)&q1, g_q1);
    cudaGetSymbolAddress((void**)&q2, g_q2);
    cudaGetSymbolAddress((void**)&k1, g_k1);
    cudaGetSymbolAddress((void**)&v1, g_v1);
    cudaGetSymbolAddress((void**)&k2, g_k2);
    cudaGetSymbolAddress((void**)&v2, g_v2);
    cudaGetSymbolAddress((void**)&sc, g_sc);
    cudaGetSymbolAddress((void**)&f1, g_f1);
    cudaGetSymbolAddress((void**)&f2, g_f2);
    cudaGetSymbolAddress((void**)&x,  g_x);

    const float inv_sqrt_l = 1.0f / 32.0f;   // 1/sqrt(1024)

    // ---- projections (NT GEMMs: x @ W.T + b) ----
    {
        dim3 gq(LATENT / 128, N_ROIS / 128);
        dim3 gk(LATENT / 128, N_BANK / 128);
        gemm128<1><<<gq, 256>>>(feat, Wc1, bc1, q1, N_ROIS, LATENT, QDIM,   1.f);
        gemm128<1><<<gk, 256>>>(bank, Wc2, bc2, k1, N_BANK, LATENT, DIM_IN, 1.f);
        gemm128<1><<<gk, 256>>>(bank, Wc3, bc3, v1, N_BANK, LATENT, DIM_IN, 1.f);
        gemm128<1><<<gq, 256>>>(feat, Wd1, bd1, q2, N_ROIS, LATENT, QDIM,   1.f);
        gemm128<1><<<gk, 256>>>(bank, Wd2, bd2, k2, N_BANK, LATENT, DIM_IN, 1.f);
        gemm128<1><<<gk, 256>>>(bank, Wd3, bd3, v2, N_BANK, LATENT, DIM_IN, 1.f);
    }

    // ---- attention branch 1 ----
    {
        dim3 gs(N_BANK / 128, N_ROIS / 128);
        dim3 gp(LATENT / 128, N_ROIS / 128);
        gemm128<1><<<gs, 256>>>(q1, k1, nullptr, sc, N_ROIS, N_BANK, LATENT, inv_sqrt_l);
        softmax8192<<<N_ROIS, 256>>>(sc);
        gemm128<0><<<gp, 256>>>(sc, v1, nullptr, f1, N_ROIS, LATENT, N_BANK, 1.f);
    }
    // ---- attention branch 2 (reuses score scratch) ----
    {
        dim3 gs(N_BANK / 128, N_ROIS / 128);
        dim3 gp(LATENT / 128, N_ROIS / 128);
        gemm128<1><<<gs, 256>>>(q2, k2, nullptr, sc, N_ROIS, N_BANK, LATENT, inv_sqrt_l);
        softmax8192<<<N_ROIS, 256>>>(sc);
        gemm128<0><<<gp, 256>>>(sc, v2, nullptr, f2, N_ROIS, LATENT, N_BANK, 1.f);
    }

    // ---- gate * LN * PReLU ----
    gate_ln_prelu<<<N_ROIS, 256>>>(f1, f2, lnw, lnb, pa, x);

    // ---- FFN: out = x @ Wffn.T + bffn ----
    {
        dim3 g(DIM_IN / 128, N_ROIS / 128);
        gemm128<1><<<g, 256>>>(x, Wffn, bffn, out, N_ROIS, DIM_IN, LATENT, 1.f);
    }
}

// round 14
// speedup vs baseline: 2.3166x; 2.3166x over previous
#include <cuda_runtime.h>
#include <cuda_bf16.h>
#include <math.h>
#include <stdint.h>
#include <stddef.h>

// Problem dims (fixed)
#define N_ROIS 4096
#define N_BANK 8192
#define QDIM   2048
#define DIM_IN 2048
#define LATENT 1024

typedef __nv_bfloat16 bf16;

// ---------------------------------------------------------------------------
// Scratch (device globals; no runtime allocation allowed)
// ---------------------------------------------------------------------------
__device__ bf16 g_feat_h[N_ROIS * QDIM],  g_feat_l[N_ROIS * QDIM];
__device__ bf16 g_bank_h[N_BANK * DIM_IN], g_bank_l[N_BANK * DIM_IN];
__device__ bf16 g_Wc1_h[LATENT * QDIM],   g_Wc1_l[LATENT * QDIM];
__device__ bf16 g_Wc2_h[LATENT * DIM_IN], g_Wc2_l[LATENT * DIM_IN];
__device__ bf16 g_Wc3_h[LATENT * DIM_IN], g_Wc3_l[LATENT * DIM_IN];
__device__ bf16 g_Wd1_h[LATENT * QDIM],   g_Wd1_l[LATENT * QDIM];
__device__ bf16 g_Wd2_h[LATENT * DIM_IN], g_Wd2_l[LATENT * DIM_IN];
__device__ bf16 g_Wd3_h[LATENT * DIM_IN], g_Wd3_l[LATENT * DIM_IN];
__device__ bf16 g_Wf_h [DIM_IN * LATENT], g_Wf_l [DIM_IN * LATENT];
__device__ bf16 g_q1_h[N_ROIS * LATENT], g_q1_l[N_ROIS * LATENT];
__device__ bf16 g_q2_h[N_ROIS * LATENT], g_q2_l[N_ROIS * LATENT];
__device__ bf16 g_k1_h[N_BANK * LATENT], g_k1_l[N_BANK * LATENT];
__device__ bf16 g_k2_h[N_BANK * LATENT], g_k2_l[N_BANK * LATENT];
__device__ float g_v1f[N_BANK * LATENT];
__device__ float g_v2f[N_BANK * LATENT];
__device__ bf16 g_v1T_h[LATENT * N_BANK], g_v1T_l[LATENT * N_BANK];
__device__ bf16 g_v2T_h[LATENT * N_BANK], g_v2T_l[LATENT * N_BANK];
__device__ float g_sc[(size_t)N_ROIS * N_BANK];
__device__ bf16 g_p_h[(size_t)N_ROIS * N_BANK], g_p_l[(size_t)N_ROIS * N_BANK];
__device__ float g_f1[N_ROIS * LATENT];
__device__ float g_f2[N_ROIS * LATENT];
__device__ bf16 g_x_h[N_ROIS * LATENT], g_x_l[N_ROIS * LATENT];

// ---------------------------------------------------------------------------
// PTX helpers (portable sm_80+ features only: mma.sync / ldmatrix / cp.async)
// ---------------------------------------------------------------------------
__device__ __forceinline__ uint32_t smem_u32(const void* p) {
    uint32_t a;
    asm("{ .reg .u64 t; cvta.to.shared.u64 t, %1; cvt.u32.u64 %0, t; }"
        : "=r"(a) : "l"(p));
    return a;
}
__device__ __forceinline__ void cp_async16(uint32_t dst, const void* src) {
    asm volatile("cp.async.cg.shared.global [%0], [%1], 16;"
                 :: "r"(dst), "l"(src) : "memory");
}
#define CP_COMMIT() asm volatile("cp.async.commit_group;" ::: "memory")
#define CP_WAIT1()  asm volatile("cp.async.wait_group 1;" ::: "memory")

#define LDSM_X4(r0, r1, r2, r3, addr) \
    asm volatile("ldmatrix.sync.aligned.m8n8.x4.shared.b16 {%0,%1,%2,%3}, [%4];" \
                 : "=r"(r0), "=r"(r1), "=r"(r2), "=r"(r3) : "r"(addr))

__device__ __forceinline__ void mma_bf16(float* c, const uint32_t* a,
                                         uint32_t b0, uint32_t b1) {
    asm volatile("mma.sync.aligned.m16n8k16.row.col.f32.bf16.bf16.f32 "
                 "{%0,%1,%2,%3}, {%4,%5,%6,%7}, {%8,%9}, {%0,%1,%2,%3};"
                 : "+f"(c[0]), "+f"(c[1]), "+f"(c[2]), "+f"(c[3])
                 : "r"(a[0]), "r"(a[1]), "r"(a[2]), "r"(a[3]), "r"(b0), "r"(b1));
}

// ---------------------------------------------------------------------------
// bf16x3 split GEMM via mma.sync:
//   C[m,n] = alpha * sum_k (Ah+Al)[m,k]*(Bh+Bl)[n,k] + bias[n]   (lo*lo dropped)
// CTA tile 128x128, BK=32, 8 warps (warp tile 32x64), 3-stage cp.async pipe.
// MODE 0: fp32 out.  MODE 1: hi/lo bf16 out.
// ---------------------------------------------------------------------------
#define ROW_B 80                   // padded row: 32 bf16 = 64B data + 16B pad
#define TILE_B (128 * ROW_B)       // 10240 B
#define STAGE_B (4 * TILE_B)       // Ah, Al, Bh, Bl
#define SMEM_B (3 * STAGE_B)       // 122880 B

template <int MODE>
__global__ void __launch_bounds__(256)
mma_gemm(const bf16* __restrict__ Ah, const bf16* __restrict__ Al,
         const bf16* __restrict__ Bh, const bf16* __restrict__ Bl,
         const float* __restrict__ bias,
         float* __restrict__ outF, bf16* __restrict__ outH, bf16* __restrict__ outL,
         int M, int N, int K, float alpha)
{
    extern __shared__ __align__(16) char smem[];
    const uint32_t sb = smem_u32(smem);
    const int tid = threadIdx.x;
    const int wid = tid >> 5;
    const int lane = tid & 31;
    const int wm = wid & 3;          // 4 m-groups of 32 rows
    const int wn = wid >> 2;         // 2 n-groups of 64 cols
    const int bm = blockIdx.y * 128;
    const int bn = blockIdx.x * 128;
    const int T = K >> 5;            // K / 32

    const bf16* tiles[4] = {Ah, Al, Bh, Bl};

    // -- loader: 2048 x 16B chunks per k-chunk; 8 per thread --
    auto issue = [&](int t, int stage) {
        const int k0 = t << 5;
        const uint32_t sbase = sb + stage * STAGE_B;
#pragma unroll
        for (int i = 0; i < 8; i++) {
            int u = tid + i * 256;
            int tile = i >> 1;               // uniform per unroll step
            int v = u & 511;
            int row = v >> 2;
            int c4 = v & 3;
            int grow = ((tile < 2) ? bm : bn) + row;
            const bf16* src = tiles[tile] + (size_t)grow * K + k0 + c4 * 8;
            cp_async16(sbase + tile * TILE_B + row * ROW_B + c4 * 16, src);
        }
    };

    float acc[2][8][4];
#pragma unroll
    for (int a = 0; a < 2; a++)
#pragma unroll
        for (int b = 0; b < 8; b++)
#pragma unroll
            for (int c = 0; c < 4; c++) acc[a][b][c] = 0.f;

    // ldmatrix lane address components
    const int lr = lane & 15;         // row within 16-row block
    const int lc = lane >> 4;         // k-half (0/1)

    issue(0, 0); CP_COMMIT();
    issue(1, 1); CP_COMMIT();

    for (int t = 0; t < T; t++) {
        CP_WAIT1();
        __syncthreads();
        if (t + 2 < T) issue(t + 2, (t + 2) % 3);
        CP_COMMIT();

        const uint32_t st = sb + (t % 3) * STAGE_B;
        const uint32_t sAh = st;
        const uint32_t sAl = st + TILE_B;
        const uint32_t sBh = st + 2 * TILE_B;
        const uint32_t sBl = st + 3 * TILE_B;

#pragma unroll
        for (int ks = 0; ks < 32; ks += 16) {
            uint32_t ah[2][4], al[2][4];
#pragma unroll
            for (int im = 0; im < 2; im++) {
                uint32_t ra = (wm * 32 + im * 16 + lr) * ROW_B + ks * 2 + lc * 16;
                LDSM_X4(ah[im][0], ah[im][1], ah[im][2], ah[im][3], sAh + ra);
                LDSM_X4(al[im][0], al[im][1], al[im][2], al[im][3], sAl + ra);
            }
#pragma unroll
            for (int j = 0; j < 4; j++) {
                uint32_t rb = (wn * 64 + j * 16 + lr) * ROW_B + ks * 2 + lc * 16;
                uint32_t bh0, bh1, bh2, bh3, bl0, bl1, bl2, bl3;
                LDSM_X4(bh0, bh1, bh2, bh3, sBh + rb);
                LDSM_X4(bl0, bl1, bl2, bl3, sBl + rb);
                // n8 frag (n0-7):  {q0,q2};  (n8-15): {q1,q3}
#pragma unroll
                for (int im = 0; im < 2; im++) {
                    mma_bf16(acc[im][2*j+0], ah[im], bh0, bh2);
                    mma_bf16(acc[im][2*j+1], ah[im], bh1, bh3);
                    mma_bf16(acc[im][2*j+0], ah[im], bl0, bl2);
                    mma_bf16(acc[im][2*j+1], ah[im], bl1, bl3);
                    mma_bf16(acc[im][2*j+0], al[im], bh0, bh2);
                    mma_bf16(acc[im][2*j+1], al[im], bh1, bh3);
                }
            }
        }
    }

    // -- epilogue --
#pragma unroll
    for (int im = 0; im < 2; im++) {
#pragma unroll
        for (int jn = 0; jn < 8; jn++) {
            int row = bm + wm * 32 + im * 16 + (lane >> 2);
            int col = bn + wn * 64 + jn * 8 + (lane & 3) * 2;
            float b0 = bias ? bias[col]     : 0.f;
            float b1 = bias ? bias[col + 1] : 0.f;
            float v0 = acc[im][jn][0] * alpha + b0;
            float v1 = acc[im][jn][1] * alpha + b1;
            float v2 = acc[im][jn][2] * alpha + b0;
            float v3 = acc[im][jn][3] * alpha + b1;
            if (MODE == 0) {
                *(float2*)(outF + (size_t)row * N + col)       = make_float2(v0, v1);
                *(float2*)(outF + (size_t)(row + 8) * N + col) = make_float2(v2, v3);
            } else {
                bf16 h0 = __float2bfloat16(v0), h1 = __float2bfloat16(v1);
                bf16 h2 = __float2bfloat16(v2), h3 = __float2bfloat16(v3);
                __nv_bfloat162 hh0; hh0.x = h0; hh0.y = h1;
                __nv_bfloat162 hh1; hh1.x = h2; hh1.y = h3;
                __nv_bfloat162 ll0, ll1;
                ll0.x = __float2bfloat16(v0 - __bfloat162float(h0));
                ll0.y = __float2bfloat16(v1 - __bfloat162float(h1));
                ll1.x = __float2bfloat16(v2 - __bfloat162float(h2));
                ll1.y = __float2bfloat16(v3 - __bfloat162float(h3));
                *(__nv_bfloat162*)(outH + (size_t)row * N + col)       = hh0;
                *(__nv_bfloat162*)(outH + (size_t)(row + 8) * N + col) = hh1;
                *(__nv_bfloat162*)(outL + (size_t)row * N + col)       = ll0;
                *(__nv_bfloat162*)(outL + (size_t)(row + 8) * N + col) = ll1;
            }
        }
    }
}

// ---------------------------------------------------------------------------
// split fp32 -> hi/lo bf16
// ---------------------------------------------------------------------------
__global__ void __launch_bounds__(256)
split_hl(const float* __restrict__ s, size_t n, bf16* __restrict__ h, bf16* __restrict__ l)
{
    size_t stride = (size_t)gridDim.x * blockDim.x * 4;
    for (size_t i = ((size_t)blockIdx.x * blockDim.x + threadIdx.x) * 4; i < n; i += stride) {
        float4 v = *(const float4*)(s + i);
        bf16 h0 = __float2bfloat16(v.x), h1 = __float2bfloat16(v.y);
        bf16 h2 = __float2bfloat16(v.z), h3 = __float2bfloat16(v.w);
        __nv_bfloat162 a, b, c, d;
        a.x = h0; a.y = h1; b.x = h2; b.y = h3;
        c.x = __float2bfloat16(v.x - __bfloat162float(h0));
        c.y = __float2bfloat16(v.y - __bfloat162float(h1));
        d.x = __float2bfloat16(v.z - __bfloat162float(h2));
        d.y = __float2bfloat16(v.w - __bfloat162float(h3));
        *(__nv_bfloat162*)(h + i)     = a;
        *(__nv_bfloat162*)(h + i + 2) = b;
        *(__nv_bfloat162*)(l + i)     = c;
        *(__nv_bfloat162*)(l + i + 2) = d;
    }
}

// ---------------------------------------------------------------------------
// transpose + split: src fp32 [R,C] -> dst hi/lo bf16 [C,R]
// ---------------------------------------------------------------------------
__global__ void __launch_bounds__(256)
transpose_split(const float* __restrict__ src, int R, int C,
                bf16* __restrict__ dh, bf16* __restrict__ dl)
{
    __shared__ float t[32][33];
    const int c0 = blockIdx.x * 32, r0 = blockIdx.y * 32;
    const int tx = threadIdx.x, ty = threadIdx.y;   // 32 x 8
#pragma unroll
    for (int i = 0; i < 32; i += 8)
        t[ty + i][tx] = src[(size_t)(r0 + ty + i) * C + c0 + tx];
    __syncthreads();
#pragma unroll
    for (int i = 0; i < 32; i += 8) {
        float v = t[tx][ty + i];
        size_t o = (size_t)(c0 + ty + i) * R + r0 + tx;
        bf16 h = __float2bfloat16(v);
        dh[o] = h;
        dl[o] = __float2bfloat16(v - __bfloat162float(h));
    }
}

// ---------------------------------------------------------------------------
// Row softmax over 8192 cols -> hi/lo bf16 probs.
// ---------------------------------------------------------------------------
__global__ void __launch_bounds__(256)
softmax8192_hl(const float* __restrict__ S, bf16* __restrict__ ph, bf16* __restrict__ pl)
{
    __shared__ float red[256];
    const int row = blockIdx.x;
    const int tid = threadIdx.x;
    const float* p = S + (size_t)row * N_BANK;

    float4 v[8];
    float lmax = -3.402823466e38f;
#pragma unroll
    for (int i = 0; i < 8; i++) {
        v[i] = *(const float4*)(p + (size_t)(i * 256 + tid) * 4);
        lmax = fmaxf(lmax, fmaxf(fmaxf(v[i].x, v[i].y), fmaxf(v[i].z, v[i].w)));
    }
    red[tid] = lmax;
    __syncthreads();
    for (int s = 128; s > 0; s >>= 1) {
        if (tid < s) red[tid] = fmaxf(red[tid], red[tid + s]);
        __syncthreads();
    }
    const float m = red[0];
    __syncthreads();
    float lsum = 0.f;
#pragma unroll
    for (int i = 0; i < 8; i++) {
        v[i].x = __expf(v[i].x - m); v[i].y = __expf(v[i].y - m);
        v[i].z = __expf(v[i].z - m); v[i].w = __expf(v[i].w - m);
        lsum += (v[i].x + v[i].y) + (v[i].z + v[i].w);
    }
    red[tid] = lsum;
    __syncthreads();
    for (int s = 128; s > 0; s >>= 1) {
        if (tid < s) red[tid] += red[tid + s];
        __syncthreads();
    }
    const float inv = 1.f / red[0];
#pragma unroll
    for (int i = 0; i < 8; i++) {
        size_t o = (size_t)row * N_BANK + (size_t)(i * 256 + tid) * 4;
        float x0 = v[i].x * inv, x1 = v[i].y * inv, x2 = v[i].z * inv, x3 = v[i].w * inv;
        bf16 h0 = __float2bfloat16(x0), h1 = __float2bfloat16(x1);
        bf16 h2 = __float2bfloat16(x2), h3 = __float2bfloat16(x3);
        __nv_bfloat162 a, b, c, d;
        a.x = h0; a.y = h1; b.x = h2; b.y = h3;
        c.x = __float2bfloat16(x0 - __bfloat162float(h0));
        c.y = __float2bfloat16(x1 - __bfloat162float(h1));
        d.x = __float2bfloat16(x2 - __bfloat162float(h2));
        d.y = __float2bfloat16(x3 - __bfloat162float(h3));
        *(__nv_bfloat162*)(ph + o)     = a;
        *(__nv_bfloat162*)(ph + o + 2) = b;
        *(__nv_bfloat162*)(pl + o)     = c;
        *(__nv_bfloat162*)(pl + o + 2) = d;
    }
}

// ---------------------------------------------------------------------------
// Gate + LayerNorm + PReLU -> hi/lo bf16
// ---------------------------------------------------------------------------
__global__ void __launch_bounds__(256)
gate_ln_prelu_hl(const float* __restrict__ f1, const float* __restrict__ f2,
                 const float* __restrict__ lnw, const float* __restrict__ lnb,
                 const float* __restrict__ pa, bf16* __restrict__ xh, bf16* __restrict__ xl)
{
    __shared__ float red[256];
    const int row = blockIdx.x;
    const int tid = threadIdx.x;
    const size_t off = (size_t)row * LATENT + tid * 4;

    float4 a = *(const float4*)(f1 + off);
    float4 b = *(const float4*)(f2 + off);
    float c0 = a.x * b.x, c1 = a.y * b.y, c2 = a.z * b.z, c3 = a.w * b.w;

    red[tid] = (c0 + c1) + (c2 + c3);
    __syncthreads();
    for (int s = 128; s > 0; s >>= 1) {
        if (tid < s) red[tid] += red[tid + s];
        __syncthreads();
    }
    const float mu = red[0] * (1.0f / LATENT);
    __syncthreads();
    float d0 = c0 - mu, d1 = c1 - mu, d2 = c2 - mu, d3 = c3 - mu;
    red[tid] = (d0 * d0 + d1 * d1) + (d2 * d2 + d3 * d3);
    __syncthreads();
    for (int s = 128; s > 0; s >>= 1) {
        if (tid < s) red[tid] += red[tid + s];
        __syncthreads();
    }
    const float rstd = rsqrtf(red[0] * (1.0f / LATENT) + 1e-5f);

    float4 w  = *(const float4*)(lnw + tid * 4);
    float4 bb = *(const float4*)(lnb + tid * 4);
    const float slope = pa[0];

    float y0 = fmaf(d0 * rstd, w.x, bb.x);
    float y1 = fmaf(d1 * rstd, w.y, bb.y);
    float y2 = fmaf(d2 * rstd, w.z, bb.z);
    float y3 = fmaf(d3 * rstd, w.w, bb.w);
    y0 = (y0 >= 0.f) ? y0 : slope * y0;
    y1 = (y1 >= 0.f) ? y1 : slope * y1;
    y2 = (y2 >= 0.f) ? y2 : slope * y2;
    y3 = (y3 >= 0.f) ? y3 : slope * y3;

    bf16 h0 = __float2bfloat16(y0), h1 = __float2bfloat16(y1);
    bf16 h2 = __float2bfloat16(y2), h3 = __float2bfloat16(y3);
    __nv_bfloat162 p0, p1, q0, q1;
    p0.x = h0; p0.y = h1; p1.x = h2; p1.y = h3;
    q0.x = __float2bfloat16(y0 - __bfloat162float(h0));
    q0.y = __float2bfloat16(y1 - __bfloat162float(h1));
    q1.x = __float2bfloat16(y2 - __bfloat162float(h2));
    q1.y = __float2bfloat16(y3 - __bfloat162float(h3));
    *(__nv_bfloat162*)(xh + off)     = p0;
    *(__nv_bfloat162*)(xh + off + 2) = p1;
    *(__nv_bfloat162*)(xl + off)     = q0;
    *(__nv_bfloat162*)(xl + off + 2) = q1;
}

// ---------------------------------------------------------------------------
// Launch
// ---------------------------------------------------------------------------
extern "C" void kernel_launch(void* const* d_in, const int* in_sizes, int n_in,
                              void* d_out, int out_size)
{
    const float* feat = (const float*)d_in[0];
    const float* bank = (const float*)d_in[1];
    const float* Wc1 = (const float*)d_in[2];  const float* bc1 = (const float*)d_in[3];
    const float* Wc2 = (const float*)d_in[4];  const float* bc2 = (const float*)d_in[5];
    const float* Wc3 = (const float*)d_in[6];  const float* bc3 = (const float*)d_in[7];
    const float* Wd1 = (const float*)d_in[8];  const float* bd1 = (const float*)d_in[9];
    const float* Wd2 = (const float*)d_in[10]; const float* bd2 = (const float*)d_in[11];
    const float* Wd3 = (const float*)d_in[12]; const float* bd3 = (const float*)d_in[13];
    const float* lnw = (const float*)d_in[14]; const float* lnb = (const float*)d_in[15];
    const float* pa  = (const float*)d_in[16];
    const float* Wffn = (const float*)d_in[17]; const float* bffn = (const float*)d_in[18];
    float* out = (float*)d_out;

    cudaFuncSetAttribute(mma_gemm<0>, cudaFuncAttributeMaxDynamicSharedMemorySize, SMEM_B);
    cudaFuncSetAttribute(mma_gemm<1>, cudaFuncAttributeMaxDynamicSharedMemorySize, SMEM_B);

#define SYM(p, s) cudaGetSymbolAddress((void**)&p, s)
    bf16 *feat_h, *feat_l, *bank_h, *bank_l;
    bf16 *Wc1h,*Wc1l,*Wc2h,*Wc2l,*Wc3h,*Wc3l,*Wd1h,*Wd1l,*Wd2h,*Wd2l,*Wd3h,*Wd3l,*Wfh,*Wfl;
    bf16 *q1h,*q1l,*q2h,*q2l,*k1h,*k1l,*k2h,*k2l;
    float *v1f,*v2f; bf16 *v1Th,*v1Tl,*v2Th,*v2Tl;
    float *sc; bf16 *ph,*pl; float *f1,*f2; bf16 *xh,*xl;
    SYM(feat_h,g_feat_h); SYM(feat_l,g_feat_l); SYM(bank_h,g_bank_h); SYM(bank_l,g_bank_l);
    SYM(Wc1h,g_Wc1_h); SYM(Wc1l,g_Wc1_l); SYM(Wc2h,g_Wc2_h); SYM(Wc2l,g_Wc2_l);
    SYM(Wc3h,g_Wc3_h); SYM(Wc3l,g_Wc3_l); SYM(Wd1h,g_Wd1_h); SYM(Wd1l,g_Wd1_l);
    SYM(Wd2h,g_Wd2_h); SYM(Wd2l,g_Wd2_l); SYM(Wd3h,g_Wd3_h); SYM(Wd3l,g_Wd3_l);
    SYM(Wfh,g_Wf_h); SYM(Wfl,g_Wf_l);
    SYM(q1h,g_q1_h); SYM(q1l,g_q1_l); SYM(q2h,g_q2_h); SYM(q2l,g_q2_l);
    SYM(k1h,g_k1_h); SYM(k1l,g_k1_l); SYM(k2h,g_k2_h); SYM(k2l,g_k2_l);
    SYM(v1f,g_v1f); SYM(v2f,g_v2f);
    SYM(v1Th,g_v1T_h); SYM(v1Tl,g_v1T_l); SYM(v2Th,g_v2T_h); SYM(v2Tl,g_v2T_l);
    SYM(sc,g_sc); SYM(ph,g_p_h); SYM(pl,g_p_l);
    SYM(f1,g_f1); SYM(f2,g_f2); SYM(xh,g_x_h); SYM(xl,g_x_l);
#undef SYM

    // ---- split inputs ----
    split_hl<<<2048, 256>>>(feat, (size_t)N_ROIS*QDIM,  feat_h, feat_l);
    split_hl<<<2048, 256>>>(bank, (size_t)N_BANK*DIM_IN, bank_h, bank_l);
    split_hl<<<1024, 256>>>(Wc1, (size_t)LATENT*QDIM,   Wc1h, Wc1l);
    split_hl<<<1024, 256>>>(Wc2, (size_t)LATENT*DIM_IN, Wc2h, Wc2l);
    split_hl<<<1024, 256>>>(Wc3, (size_t)LATENT*DIM_IN, Wc3h, Wc3l);
    split_hl<<<1024, 256>>>(Wd1, (size_t)LATENT*QDIM,   Wd1h, Wd1l);
    split_hl<<<1024, 256>>>(Wd2, (size_t)LATENT*DIM_IN, Wd2h, Wd2l);
    split_hl<<<1024, 256>>>(Wd3, (size_t)LATENT*DIM_IN, Wd3h, Wd3l);
    split_hl<<<1024, 256>>>(Wffn, (size_t)DIM_IN*LATENT, Wfh, Wfl);

    const float inv_sqrt_l = 1.0f / 32.0f;   // 1/sqrt(1024)

    // ---- projections ----
    {
        dim3 gq(LATENT/128, N_ROIS/128);
        dim3 gk(LATENT/128, N_BANK/128);
        mma_gemm<1><<<gq, 256, SMEM_B>>>(feat_h, feat_l, Wc1h, Wc1l, bc1, nullptr, q1h, q1l, N_ROIS, LATENT, QDIM, 1.f);
        mma_gemm<1><<<gk, 256, SMEM_B>>>(bank_h, bank_l, Wc2h, Wc2l, bc2, nullptr, k1h, k1l, N_BANK, LATENT, DIM_IN, 1.f);
        mma_gemm<0><<<gk, 256, SMEM_B>>>(bank_h, bank_l, Wc3h, Wc3l, bc3, v1f, nullptr, nullptr, N_BANK, LATENT, DIM_IN, 1.f);
        mma_gemm<1><<<gq, 256, SMEM_B>>>(feat_h, feat_l, Wd1h, Wd1l, bd1, nullptr, q2h, q2l, N_ROIS, LATENT, QDIM, 1.f);
        mma_gemm<1><<<gk, 256, SMEM_B>>>(bank_h, bank_l, Wd2h, Wd2l, bd2, nullptr, k2h, k2l, N_BANK, LATENT, DIM_IN, 1.f);
        mma_gemm<0><<<gk, 256, SMEM_B>>>(bank_h, bank_l, Wd3h, Wd3l, bd3, v2f, nullptr, nullptr, N_BANK, LATENT, DIM_IN, 1.f);
    }
    // ---- V transposes ----
    {
        dim3 gt(LATENT/32, N_BANK/32);
        dim3 bt(32, 8);
        transpose_split<<<gt, bt>>>(v1f, N_BANK, LATENT, v1Th, v1Tl);
        transpose_split<<<gt, bt>>>(v2f, N_BANK, LATENT, v2Th, v2Tl);
    }
    // ---- attention branch 1 ----
    {
        dim3 gs(N_BANK/128, N_ROIS/128);
        dim3 gp(LATENT/128, N_ROIS/128);
        mma_gemm<0><<<gs, 256, SMEM_B>>>(q1h, q1l, k1h, k1l, nullptr, sc, nullptr, nullptr, N_ROIS, N_BANK, LATENT, inv_sqrt_l);
        softmax8192_hl<<<N_ROIS, 256>>>(sc, ph, pl);
        mma_gemm<0><<<gp, 256, SMEM_B>>>(ph, pl, v1Th, v1Tl, nullptr, f1, nullptr, nullptr, N_ROIS, LATENT, N_BANK, 1.f);
    }
    // ---- attention branch 2 ----
    {
        dim3 gs(N_BANK/128, N_ROIS/128);
        dim3 gp(LATENT/128, N_ROIS/128);
        mma_gemm<0><<<gs, 256, SMEM_B>>>(q2h, q2l, k2h, k2l, nullptr, sc, nullptr, nullptr, N_ROIS, N_BANK, LATENT, inv_sqrt_l);
        softmax8192_hl<<<N_ROIS, 256>>>(sc, ph, pl);
        mma_gemm<0><<<gp, 256, SMEM_B>>>(ph, pl, v2Th, v2Tl, nullptr, f2, nullptr, nullptr, N_ROIS, LATENT, N_BANK, 1.f);
    }
    // ---- gate * LN * PReLU ----
    gate_ln_prelu_hl<<<N_ROIS, 256>>>(f1, f2, lnw, lnb, pa, xh, xl);

    // ---- FFN ----
    {
        dim3 g(DIM_IN/128, N_ROIS/128);
        mma_gemm<0><<<g, 256, SMEM_B>>>(xh, xl, Wfh, Wfl, bffn, out, nullptr, nullptr, N_ROIS, DIM_IN, LATENT, 1.f);
    }
}